// round 1
// baseline (speedup 1.0000x reference)
#include <cuda_runtime.h>
#include <math.h>

// ---------------------------------------------------------------------------
// Problem constants
// ---------------------------------------------------------------------------
#define NN      50000
#define EE      1000000
#define EH      500000
#define ND      256
#define EDIM    64
#define RBFD    32
#define KIN     101     // 64 + 5 + 32
#define KPAD    104
#define INV_SIG 3.2f    // 1 / (10/32)

// padded node count for the intermediate h buffer (782 blocks * 64 = 50048)
#define NPAD    50048

// scratch: h = r_x + r_v + r_a  (pre-activation input to W_n GEMM)
__device__ float g_h[(size_t)NPAD * ND];

__device__ __forceinline__ float silu_f(float x) {
    return x / (1.0f + __expf(-x));
}

// ---------------------------------------------------------------------------
// Kernel 1: node pre-GEMM.  u = [rbf(|x_t-dst_x|) (32) | pairwise |v| (16) |
// dst_a (16)],  h = u @ Wc + (b_x+b_v+b_a),  Wc = [W_x; W_v; W_a] (64 x 256).
// Block: 256 threads, 64 nodes.  C-tile per thread: 8 nodes x 8 cols.
// smem: Wc 64KB + u 16KB + bsum 1KB + dnorm 256B
// ---------------------------------------------------------------------------
__global__ void __launch_bounds__(256)
node_pre_kernel(const float* __restrict__ x_t, const float* __restrict__ v_t,
                const float* __restrict__ dst_x, const float* __restrict__ dst_v,
                const float* __restrict__ dst_a,
                const float* __restrict__ W_x, const float* __restrict__ b_x,
                const float* __restrict__ W_v, const float* __restrict__ b_v,
                const float* __restrict__ W_a, const float* __restrict__ b_a)
{
    extern __shared__ __align__(16) float smem[];
    float* Wc    = smem;                 // 64*256
    float* u     = smem + 64 * 256;      // 64*64
    float* bsum  = smem + 64 * 256 + 64 * 64;   // 256
    float* dnorm = bsum + 256;           // 64

    const int tid = threadIdx.x;
    const int n0  = blockIdx.x * 64;

    // stage combined weight Wc = [W_x(32 rows); W_v(16); W_a(16)]
    for (int f = tid; f < 32 * 64; f += 256)
        ((float4*)Wc)[f] = ((const float4*)W_x)[f];
    for (int f = tid; f < 16 * 64; f += 256)
        ((float4*)(Wc + 32 * 256))[f] = ((const float4*)W_v)[f];
    for (int f = tid; f < 16 * 64; f += 256)
        ((float4*)(Wc + 48 * 256))[f] = ((const float4*)W_a)[f];
    bsum[tid] = b_x[tid] + b_v[tid] + b_a[tid];

    // per-node feature staging: threads 0..63 each own one node
    if (tid < 64) {
        int n = n0 + tid;
        if (n < NN) {
            float d0 = x_t[n * 3 + 0] - dst_x[n * 3 + 0];
            float d1 = x_t[n * 3 + 1] - dst_x[n * 3 + 1];
            float d2 = x_t[n * 3 + 2] - dst_x[n * 3 + 2];
            dnorm[tid] = sqrtf(fmaxf(d0 * d0 + d1 * d1 + d2 * d2, 1e-8f));

            float v[12], w[12];
            #pragma unroll
            for (int i = 0; i < 12; i++) {
                v[i] = v_t[n * 12 + i];
                w[i] = dst_v[n * 12 + i];
            }
            #pragma unroll
            for (int c1 = 0; c1 < 4; c1++) {
                #pragma unroll
                for (int c2 = 0; c2 < 4; c2++) {
                    float a0 = v[c1 * 3 + 0] - w[c2 * 3 + 0];
                    float a1 = v[c1 * 3 + 1] - w[c2 * 3 + 1];
                    float a2 = v[c1 * 3 + 2] - w[c2 * 3 + 2];
                    float ss = a0 * a0 + a1 * a1 + a2 * a2;
                    u[tid * 64 + 32 + c1 * 4 + c2] = sqrtf(fmaxf(ss, 1e-8f));
                }
            }
            #pragma unroll
            for (int j = 0; j < 16; j++)
                u[tid * 64 + 48 + j] = dst_a[n * 16 + j];
        } else {
            dnorm[tid] = 0.0f;
            #pragma unroll
            for (int j = 0; j < 32; j++)
                u[tid * 64 + 32 + j] = 0.0f;
        }
    }
    __syncthreads();

    // RBF of node distance (spread across all 8 warps)
    {
        int e  = tid >> 2;
        int k0 = (tid & 3) * 8;
        float d = dnorm[e];
        #pragma unroll
        for (int kk = 0; kk < 8; kk++) {
            int k = k0 + kk;
            float t = (d - 10.0f * (float)k / 31.0f) * INV_SIG;
            u[e * 64 + k] = __expf(-t * t);
        }
    }
    __syncthreads();

    // GEMM1: [64 x 64] @ [64 x 256]
    const int tx = tid & 31;   // col group: cols tx*4..+3 and 128+tx*4..+3
    const int ty = tid >> 5;   // node group: nodes ty*8..+7
    float acc[8][8];
    #pragma unroll
    for (int i = 0; i < 8; i++)
        #pragma unroll
        for (int j = 0; j < 8; j++)
            acc[i][j] = 0.0f;

    for (int k = 0; k < 64; k++) {
        float4 b0 = *(const float4*)&Wc[k * 256 + tx * 4];
        float4 b1 = *(const float4*)&Wc[k * 256 + 128 + tx * 4];
        #pragma unroll
        for (int i = 0; i < 8; i++) {
            float a = u[(ty * 8 + i) * 64 + k];  // warp-broadcast
            acc[i][0] += a * b0.x; acc[i][1] += a * b0.y;
            acc[i][2] += a * b0.z; acc[i][3] += a * b0.w;
            acc[i][4] += a * b1.x; acc[i][5] += a * b1.y;
            acc[i][6] += a * b1.z; acc[i][7] += a * b1.w;
        }
    }

    float4 bs0 = *(const float4*)&bsum[tx * 4];
    float4 bs1 = *(const float4*)&bsum[128 + tx * 4];
    #pragma unroll
    for (int i = 0; i < 8; i++) {
        int n = n0 + ty * 8 + i;   // n < NPAD always; padded rows harmless
        float4 o0, o1;
        o0.x = acc[i][0] + bs0.x; o0.y = acc[i][1] + bs0.y;
        o0.z = acc[i][2] + bs0.z; o0.w = acc[i][3] + bs0.w;
        o1.x = acc[i][4] + bs1.x; o1.y = acc[i][5] + bs1.y;
        o1.z = acc[i][6] + bs1.z; o1.w = acc[i][7] + bs1.w;
        *(float4*)&g_h[(size_t)n * 256 + tx * 4]       = o0;
        *(float4*)&g_h[(size_t)n * 256 + 128 + tx * 4] = o1;
    }
}

// ---------------------------------------------------------------------------
// Kernel 2: node main GEMM.  out = s_t + silu(h @ W_n + b_n)
// Block: 256 threads, 64 nodes.  K=256 in 4 chunks of 64 (W_n chunk staged).
// smem: htile 16KB + Wn chunk 64KB
// ---------------------------------------------------------------------------
__global__ void __launch_bounds__(256)
node_gemm_kernel(const float* __restrict__ s_t,
                 const float* __restrict__ W_n, const float* __restrict__ b_n,
                 float* __restrict__ node_out)
{
    extern __shared__ __align__(16) float smem[];
    float* ht  = smem;               // 64 x 64
    float* Wns = smem + 64 * 64;     // 64 x 256

    const int tid = threadIdx.x;
    const int n0  = blockIdx.x * 64;
    const int tx  = tid & 31;
    const int ty  = tid >> 5;

    float4 bn0 = *(const float4*)&b_n[tx * 4];
    float4 bn1 = *(const float4*)&b_n[128 + tx * 4];

    float acc[8][8];
    #pragma unroll
    for (int i = 0; i < 8; i++)
        #pragma unroll
        for (int j = 0; j < 8; j++)
            acc[i][j] = 0.0f;

    for (int kc = 0; kc < 4; kc++) {
        __syncthreads();
        // stage h tile [64 nodes x 64 k]
        for (int f = tid; f < 64 * 16; f += 256) {
            int e = f >> 4, q = f & 15;
            ((float4*)ht)[e * 16 + q] =
                ((const float4*)g_h)[(size_t)(n0 + e) * 64 + kc * 16 + q];
        }
        // stage W_n chunk [64 k x 256]
        for (int f = tid; f < 64 * 64; f += 256)
            ((float4*)Wns)[f] = ((const float4*)W_n)[kc * 4096 + f];
        __syncthreads();

        for (int k = 0; k < 64; k++) {
            float4 b0 = *(const float4*)&Wns[k * 256 + tx * 4];
            float4 b1 = *(const float4*)&Wns[k * 256 + 128 + tx * 4];
            #pragma unroll
            for (int i = 0; i < 8; i++) {
                float a = ht[(ty * 8 + i) * 64 + k];  // warp-broadcast
                acc[i][0] += a * b0.x; acc[i][1] += a * b0.y;
                acc[i][2] += a * b0.z; acc[i][3] += a * b0.w;
                acc[i][4] += a * b1.x; acc[i][5] += a * b1.y;
                acc[i][6] += a * b1.z; acc[i][7] += a * b1.w;
            }
        }
    }

    #pragma unroll
    for (int i = 0; i < 8; i++) {
        int n = n0 + ty * 8 + i;
        if (n < NN) {
            float4 s0 = *(const float4*)&s_t[(size_t)n * 256 + tx * 4];
            float4 s1 = *(const float4*)&s_t[(size_t)n * 256 + 128 + tx * 4];
            float4 o0, o1;
            o0.x = s0.x + silu_f(acc[i][0] + bn0.x);
            o0.y = s0.y + silu_f(acc[i][1] + bn0.y);
            o0.z = s0.z + silu_f(acc[i][2] + bn0.z);
            o0.w = s0.w + silu_f(acc[i][3] + bn0.w);
            o1.x = s1.x + silu_f(acc[i][4] + bn1.x);
            o1.y = s1.y + silu_f(acc[i][5] + bn1.y);
            o1.z = s1.z + silu_f(acc[i][6] + bn1.z);
            o1.w = s1.w + silu_f(acc[i][7] + bn1.w);
            *(float4*)&node_out[(size_t)n * 256 + tx * 4]       = o0;
            *(float4*)&node_out[(size_t)n * 256 + 128 + tx * 4] = o1;
        }
    }
}

// ---------------------------------------------------------------------------
// Kernel 3: edge residual.
// edge_in = [e_t(64) | dst_e(5) | rbf(d1)-rbf(dt) (32)] -> 101 (pad 104)
// out = silu(edge_in @ W_e + b_e), written to rows j and j+E_HALF.
// Block: 256 threads, 128 edges.  C-tile per thread: 8 edges x 4 cols.
// smem: Ws 104x64 + A 128x104 + b_e + dt/d1
// ---------------------------------------------------------------------------
__global__ void __launch_bounds__(256)
edge_kernel(const float* __restrict__ e_t,  const float* __restrict__ dst_e,
            const int*   __restrict__ edge_src, const int* __restrict__ edge_dst,
            const float* __restrict__ x_t,  const float* __restrict__ dst_x,
            const float* __restrict__ W_e,  const float* __restrict__ b_e,
            float* __restrict__ edge_out)
{
    extern __shared__ __align__(16) float smem[];
    float* Ws  = smem;                       // 104 * 64
    float* As  = smem + KPAD * 64;           // 128 * 104
    float* bes = As + 128 * KPAD;            // 64
    float* dts = bes + 64;                   // 128
    float* d1s = dts + 128;                  // 128

    const int tid = threadIdx.x;
    const int j0  = blockIdx.x * 128;

    // stage W_e (101 rows) + zero pad rows 101..103
    for (int f = tid; f < 101 * 16; f += 256)
        ((float4*)Ws)[f] = ((const float4*)W_e)[f];
    for (int f = tid; f < 3 * 64; f += 256)
        Ws[101 * 64 + f] = 0.0f;
    if (tid < 64) bes[tid] = b_e[tid];

    // stage e_t tile: 128 rows x 16 float4 (reads stay < E rows, always valid)
    for (int f = tid; f < 128 * 16; f += 256) {
        int e = f >> 4, q = f & 15;
        *(float4*)&As[e * KPAD + q * 4] = ((const float4*)e_t)[(size_t)(j0 + e) * 16 + q];
    }
    // stage dst_e (5 cols) with tail guard
    for (int f = tid; f < 128 * 5; f += 256) {
        int e = f / 5, q = f - e * 5;
        As[e * KPAD + 64 + q] = (j0 + e < EH) ? dst_e[(size_t)(j0 + e) * 5 + q] : 0.0f;
    }
    // zero A pad columns
    if (tid < 128) {
        As[tid * KPAD + 101] = 0.0f;
        As[tid * KPAD + 102] = 0.0f;
        As[tid * KPAD + 103] = 0.0f;
    }
    // gather node positions, compute the two distances
    if (tid < 128) {
        int j = j0 + tid;            // j < 500096 <= E-1, index reads valid
        int s = edge_src[j];
        int d = edge_dst[j];
        float a0 = x_t[s * 3 + 0] - x_t[d * 3 + 0];
        float a1 = x_t[s * 3 + 1] - x_t[d * 3 + 1];
        float a2 = x_t[s * 3 + 2] - x_t[d * 3 + 2];
        dts[tid] = sqrtf(fmaxf(a0 * a0 + a1 * a1 + a2 * a2, 1e-8f));
        float c0 = dst_x[s * 3 + 0] - dst_x[d * 3 + 0];
        float c1 = dst_x[s * 3 + 1] - dst_x[d * 3 + 1];
        float c2 = dst_x[s * 3 + 2] - dst_x[d * 3 + 2];
        d1s[tid] = sqrtf(fmaxf(c0 * c0 + c1 * c1 + c2 * c2, 1e-8f));
    }
    __syncthreads();

    // d_in = rbf(d1) - rbf(dt), spread across all warps (16 k per thread)
    {
        int e  = tid >> 1;
        int k0 = (tid & 1) * 16;
        float v1 = d1s[e], vt = dts[e];
        #pragma unroll
        for (int kk = 0; kk < 16; kk++) {
            int k = k0 + kk;
            float mu = 10.0f * (float)k / 31.0f;
            float t1 = (v1 - mu) * INV_SIG;
            float t2 = (vt - mu) * INV_SIG;
            As[e * KPAD + 69 + k] = __expf(-t1 * t1) - __expf(-t2 * t2);
        }
    }
    __syncthreads();

    // GEMM: [128 x 104] @ [104 x 64]
    const int tx = tid & 15;   // cols tx*4..+3
    const int ty = tid >> 4;   // edges ty*8..+7
    float acc[8][4];
    #pragma unroll
    for (int i = 0; i < 8; i++)
        #pragma unroll
        for (int j = 0; j < 4; j++)
            acc[i][j] = 0.0f;

    for (int k = 0; k < KPAD; k++) {
        float4 b = *(const float4*)&Ws[k * 64 + tx * 4];
        #pragma unroll
        for (int i = 0; i < 8; i++) {
            float a = As[(ty * 8 + i) * KPAD + k];  // 2-way broadcast per warp
            acc[i][0] += a * b.x; acc[i][1] += a * b.y;
            acc[i][2] += a * b.z; acc[i][3] += a * b.w;
        }
    }

    float4 be = *(const float4*)&bes[tx * 4];
    #pragma unroll
    for (int i = 0; i < 8; i++) {
        int j = j0 + ty * 8 + i;
        if (j < EH) {
            float4 r;
            r.x = silu_f(acc[i][0] + be.x);
            r.y = silu_f(acc[i][1] + be.y);
            r.z = silu_f(acc[i][2] + be.z);
            r.w = silu_f(acc[i][3] + be.w);
            *(float4*)&edge_out[(size_t)j * 64 + tx * 4]        = r;
            *(float4*)&edge_out[(size_t)(j + EH) * 64 + tx * 4] = r;
        }
    }
}

// ---------------------------------------------------------------------------
// Host launch.  Inputs resolved BY ELEMENT COUNT (robust to metadata ordering:
// relative order of equal-size pairs is identical in both dict-order and
// reference-signature order).
// ---------------------------------------------------------------------------
static int find_by_size(const int* sizes, int n, int target, int occurrence) {
    int seen = 0;
    for (int i = 0; i < n; i++) {
        if (sizes[i] == target) {
            if (seen == occurrence) return i;
            seen++;
        }
    }
    return -1;
}

extern "C" void kernel_launch(void* const* d_in, const int* in_sizes, int n_in,
                              void* d_out, int out_size)
{
    const float* s_t   = (const float*)d_in[find_by_size(in_sizes, n_in, NN * ND, 0)];
    const float* x_t   = (const float*)d_in[find_by_size(in_sizes, n_in, NN * 3, 0)];
    const float* dst_x = (const float*)d_in[find_by_size(in_sizes, n_in, NN * 3, 1)];
    const float* v_t   = (const float*)d_in[find_by_size(in_sizes, n_in, NN * 12, 0)];
    const float* dst_v = (const float*)d_in[find_by_size(in_sizes, n_in, NN * 12, 1)];
    const float* e_t   = (const float*)d_in[find_by_size(in_sizes, n_in, EE * EDIM, 0)];
    const float* dst_a = (const float*)d_in[find_by_size(in_sizes, n_in, NN * 16, 0)];
    const float* dst_e = (const float*)d_in[find_by_size(in_sizes, n_in, EH * 5, 0)];
    const int* edge_src = (const int*)d_in[find_by_size(in_sizes, n_in, EE, 0)];
    const int* edge_dst = (const int*)d_in[find_by_size(in_sizes, n_in, EE, 1)];
    const float* W_x = (const float*)d_in[find_by_size(in_sizes, n_in, 32 * 256, 0)];
    const float* W_v = (const float*)d_in[find_by_size(in_sizes, n_in, 16 * 256, 0)];
    const float* W_a = (const float*)d_in[find_by_size(in_sizes, n_in, 16 * 256, 1)];
    const float* W_n = (const float*)d_in[find_by_size(in_sizes, n_in, 256 * 256, 0)];
    const float* W_e = (const float*)d_in[find_by_size(in_sizes, n_in, 101 * 64, 0)];
    const float* b_x = (const float*)d_in[find_by_size(in_sizes, n_in, 256, 0)];
    const float* b_v = (const float*)d_in[find_by_size(in_sizes, n_in, 256, 1)];
    const float* b_a = (const float*)d_in[find_by_size(in_sizes, n_in, 256, 2)];
    const float* b_n = (const float*)d_in[find_by_size(in_sizes, n_in, 256, 3)];
    const float* b_e = (const float*)d_in[find_by_size(in_sizes, n_in, 64, 0)];

    float* out      = (float*)d_out;
    float* node_out = out;
    float* edge_out = out + (size_t)NN * ND;

    const int SMEM_N1 = (64 * 256 + 64 * 64 + 256 + 64) * 4;           // 83200
    const int SMEM_N2 = (64 * 64 + 64 * 256) * 4;                      // 81920
    const int SMEM_E  = (KPAD * 64 + 128 * KPAD + 64 + 128 + 128) * 4; // 81152

    cudaFuncSetAttribute(node_pre_kernel,
                         cudaFuncAttributeMaxDynamicSharedMemorySize, SMEM_N1);
    cudaFuncSetAttribute(node_gemm_kernel,
                         cudaFuncAttributeMaxDynamicSharedMemorySize, SMEM_N2);
    cudaFuncSetAttribute(edge_kernel,
                         cudaFuncAttributeMaxDynamicSharedMemorySize, SMEM_E);

    const int NODE_BLOCKS = (NN + 63) / 64;     // 782
    const int EDGE_BLOCKS = (EH + 127) / 128;   // 3907

    node_pre_kernel<<<NODE_BLOCKS, 256, SMEM_N1>>>(
        x_t, v_t, dst_x, dst_v, dst_a, W_x, b_x, W_v, b_v, W_a, b_a);
    edge_kernel<<<EDGE_BLOCKS, 256, SMEM_E>>>(
        e_t, dst_e, edge_src, edge_dst, x_t, dst_x, W_e, b_e, edge_out);
    node_gemm_kernel<<<NODE_BLOCKS, 256, SMEM_N2>>>(
        s_t, W_n, b_n, node_out);
}

// round 2
// speedup vs baseline: 1.9041x; 1.9041x over previous
#include <cuda_runtime.h>
#include <math.h>

// ---------------------------------------------------------------------------
// Problem constants
// ---------------------------------------------------------------------------
#define NN      50000
#define EE      1000000
#define EH      500000
#define ND      256
#define INV_SIG 3.2f    // 1 / (10/32)

#define ESTR    108     // edge A/W smem stride (12 mod 32 -> conflict-free frags)
#define USTR    68      // node u/M smem stride (4 mod 32 -> conflict-free frags)

// Precomputed fused node weights: M = [W_x;W_v;W_a] @ W_n  (64 x 256),
// c = (b_x+b_v+b_a) @ W_n + b_n (256)
__device__ float g_M[64 * 256];
__device__ float g_c[256];

__device__ __forceinline__ float silu_f(float x) {
    return x / (1.0f + __expf(-x));
}

// round-to-nearest tf32 (value kept in a float register, low mantissa zeroed)
__device__ __forceinline__ float tf32r(float x) {
    unsigned r;
    asm("cvt.rna.tf32.f32 %0, %1;" : "=r"(r) : "f"(x));
    return __uint_as_float(r);
}

// m16n8k8 tf32 mma, row-major A, col-major B, fp32 accumulate
__device__ __forceinline__ void mma_tf32(float& c0, float& c1, float& c2, float& c3,
                                         float a0, float a1, float a2, float a3,
                                         float b0, float b1) {
    asm volatile(
        "mma.sync.aligned.m16n8k8.row.col.f32.tf32.tf32.f32 "
        "{%0,%1,%2,%3}, {%4,%5,%6,%7}, {%8,%9}, {%0,%1,%2,%3};\n"
        : "+f"(c0), "+f"(c1), "+f"(c2), "+f"(c3)
        : "r"(__float_as_uint(a0)), "r"(__float_as_uint(a1)),
          "r"(__float_as_uint(a2)), "r"(__float_as_uint(a3)),
          "r"(__float_as_uint(b0)), "r"(__float_as_uint(b1)));
}

// ---------------------------------------------------------------------------
// Kernel 0: fold the two node GEMMs into one: M = Wc@W_n, c = bsum@W_n + b_n.
// 65 blocks x 256 threads (block 64 computes c). fp32, tiny.
// ---------------------------------------------------------------------------
__global__ void __launch_bounds__(256)
precompute_kernel(const float* __restrict__ W_x, const float* __restrict__ W_v,
                  const float* __restrict__ W_a,
                  const float* __restrict__ b_x, const float* __restrict__ b_v,
                  const float* __restrict__ b_a,
                  const float* __restrict__ W_n, const float* __restrict__ b_n)
{
    __shared__ float row[256];
    const int i = blockIdx.x;
    const int j = threadIdx.x;

    if (i < 64) {
        const float* src = (i < 32) ? &W_x[i * 256]
                         : (i < 48) ? &W_v[(i - 32) * 256]
                                    : &W_a[(i - 48) * 256];
        row[j] = src[j];
        __syncthreads();
        float acc = 0.0f;
        #pragma unroll 8
        for (int k = 0; k < 256; k++)
            acc += row[k] * W_n[k * 256 + j];
        g_M[i * 256 + j] = acc;
    } else {
        row[j] = b_x[j] + b_v[j] + b_a[j];
        __syncthreads();
        float acc = b_n[j];
        #pragma unroll 8
        for (int k = 0; k < 256; k++)
            acc += row[k] * W_n[k * 256 + j];
        g_c[j] = acc;
    }
}

// ---------------------------------------------------------------------------
// Kernel 1: node path.  u = [rbf(32) | |v-pairs|(16) | dst_a(16)]  (K=64)
// node_out = s_t + silu(u @ M + c)  via tf32 mma.
// Block: 256 threads (8 warps), 64 nodes x 256 cols.
// Warp (w): rows (w/4)*32..+31 (2 m-tiles), cols (w%4)*64..+63 (8 n-tiles).
// ---------------------------------------------------------------------------
__global__ void __launch_bounds__(256, 2)
node_kernel(const float* __restrict__ s_t, const float* __restrict__ x_t,
            const float* __restrict__ v_t, const float* __restrict__ dst_x,
            const float* __restrict__ dst_v, const float* __restrict__ dst_a,
            float* __restrict__ node_out)
{
    extern __shared__ __align__(16) float smem[];
    float* MT = smem;                    // 256 x USTR  (MT[n][k] = M[k][n], tf32)
    float* u  = smem + 256 * USTR;       // 64 x USTR
    float* cb = u + 64 * USTR;           // 256
    float* dn = cb + 256;                // 64

    const int tid = threadIdx.x;
    const int n0b = blockIdx.x * 64;

    // stage MT (transpose + tf32 round)
    for (int f = tid; f < 64 * 256; f += 256) {
        int k = f >> 8, n = f & 255;
        MT[n * USTR + k] = tf32r(g_M[f]);
    }
    cb[tid] = g_c[tid];

    // per-node features
    if (tid < 64) {
        int n = n0b + tid;
        if (n < NN) {
            float d0 = x_t[n * 3 + 0] - dst_x[n * 3 + 0];
            float d1 = x_t[n * 3 + 1] - dst_x[n * 3 + 1];
            float d2 = x_t[n * 3 + 2] - dst_x[n * 3 + 2];
            dn[tid] = sqrtf(fmaxf(d0 * d0 + d1 * d1 + d2 * d2, 1e-8f));

            float v[12], w[12];
            #pragma unroll
            for (int i = 0; i < 12; i++) {
                v[i] = v_t[n * 12 + i];
                w[i] = dst_v[n * 12 + i];
            }
            #pragma unroll
            for (int c1 = 0; c1 < 4; c1++)
                #pragma unroll
                for (int c2 = 0; c2 < 4; c2++) {
                    float a0 = v[c1 * 3 + 0] - w[c2 * 3 + 0];
                    float a1 = v[c1 * 3 + 1] - w[c2 * 3 + 1];
                    float a2 = v[c1 * 3 + 2] - w[c2 * 3 + 2];
                    u[tid * USTR + 32 + c1 * 4 + c2] =
                        tf32r(sqrtf(fmaxf(a0 * a0 + a1 * a1 + a2 * a2, 1e-8f)));
                }
            #pragma unroll
            for (int j = 0; j < 16; j++)
                u[tid * USTR + 48 + j] = tf32r(dst_a[n * 16 + j]);
        } else {
            dn[tid] = 0.0f;
            #pragma unroll
            for (int j = 0; j < 32; j++)
                u[tid * USTR + 32 + j] = 0.0f;
        }
    }
    __syncthreads();

    // rbf cols 0..31 (spread across all warps)
    {
        int e = tid >> 2, k0 = (tid & 3) * 8;
        float d = dn[e];
        #pragma unroll
        for (int kk = 0; kk < 8; kk++) {
            int k = k0 + kk;
            float t = (d - 10.0f * (float)k / 31.0f) * INV_SIG;
            u[e * USTR + k] = tf32r(__expf(-t * t));
        }
    }
    __syncthreads();

    const int w = tid >> 5, lane = tid & 31;
    const int g = lane >> 2, t = lane & 3;
    const int m0 = (w >> 2) * 32, n0 = (w & 3) * 64;

    float acc[2][8][4];
    #pragma unroll
    for (int mt = 0; mt < 2; mt++)
        #pragma unroll
        for (int nt = 0; nt < 8; nt++)
            #pragma unroll
            for (int q = 0; q < 4; q++)
                acc[mt][nt][q] = 0.0f;

    #pragma unroll
    for (int ks = 0; ks < 8; ks++) {
        const int k0 = ks * 8;
        float a[2][4];
        #pragma unroll
        for (int mt = 0; mt < 2; mt++) {
            int r = m0 + mt * 16 + g;
            a[mt][0] = u[r * USTR + k0 + t];
            a[mt][1] = u[(r + 8) * USTR + k0 + t];
            a[mt][2] = u[r * USTR + k0 + t + 4];
            a[mt][3] = u[(r + 8) * USTR + k0 + t + 4];
        }
        #pragma unroll
        for (int nt = 0; nt < 8; nt++) {
            int nnc = n0 + nt * 8 + g;
            float b0 = MT[nnc * USTR + k0 + t];
            float b1 = MT[nnc * USTR + k0 + t + 4];
            mma_tf32(acc[0][nt][0], acc[0][nt][1], acc[0][nt][2], acc[0][nt][3],
                     a[0][0], a[0][1], a[0][2], a[0][3], b0, b1);
            mma_tf32(acc[1][nt][0], acc[1][nt][1], acc[1][nt][2], acc[1][nt][3],
                     a[1][0], a[1][1], a[1][2], a[1][3], b0, b1);
        }
    }

    // epilogue: out = s_t + silu(acc + c)
    #pragma unroll
    for (int mt = 0; mt < 2; mt++) {
        #pragma unroll
        for (int nt = 0; nt < 8; nt++) {
            int col = n0 + nt * 8 + 2 * t;
            float c0v = cb[col], c1v = cb[col + 1];
            int r0 = n0b + m0 + mt * 16 + g;
            if (r0 < NN) {
                float2 s = *(const float2*)&s_t[(size_t)r0 * 256 + col];
                float2 o;
                o.x = s.x + silu_f(acc[mt][nt][0] + c0v);
                o.y = s.y + silu_f(acc[mt][nt][1] + c1v);
                *(float2*)&node_out[(size_t)r0 * 256 + col] = o;
            }
            int r1 = r0 + 8;
            if (r1 < NN) {
                float2 s = *(const float2*)&s_t[(size_t)r1 * 256 + col];
                float2 o;
                o.x = s.x + silu_f(acc[mt][nt][2] + c0v);
                o.y = s.y + silu_f(acc[mt][nt][3] + c1v);
                *(float2*)&node_out[(size_t)r1 * 256 + col] = o;
            }
        }
    }
}

// ---------------------------------------------------------------------------
// Kernel 2: edge path.  A = [e_t(64)|dst_e(5)|rbf(d1)-rbf(dt)(32)|0 pad] K=104
// out = silu(A @ W_e + b_e), mirrored write to rows j and j+EH.  tf32 mma.
// Block: 256 threads (8 warps), 128 edges x 64 cols; warp w: rows w*16..+15.
// ---------------------------------------------------------------------------
__global__ void __launch_bounds__(256, 2)
edge_kernel(const float* __restrict__ e_t, const float* __restrict__ dst_e,
            const int* __restrict__ edge_src, const int* __restrict__ edge_dst,
            const float* __restrict__ x_t, const float* __restrict__ dst_x,
            const float* __restrict__ W_e, const float* __restrict__ b_e,
            float* __restrict__ edge_out)
{
    extern __shared__ __align__(16) float smem[];
    float* Ws  = smem;                    // 64 x ESTR  (Ws[n][k] = W_e[k][n], tf32)
    float* As  = smem + 64 * ESTR;        // 128 x ESTR
    float* bes = As + 128 * ESTR;         // 64
    float* dts = bes + 64;                // 128
    float* d1s = dts + 128;               // 128

    const int tid = threadIdx.x;
    const int j0  = blockIdx.x * 128;

    // stage W_e transposed (+ zero pad rows 101..103)
    for (int f = tid; f < 104 * 64; f += 256) {
        int k = f >> 6, n = f & 63;
        Ws[n * ESTR + k] = (k < 101) ? tf32r(W_e[k * 64 + n]) : 0.0f;
    }
    if (tid < 64) bes[tid] = b_e[tid];

    // e_t cols 0..63 (rows j0..j0+127 always < EE)
    for (int f = tid; f < 128 * 16; f += 256) {
        int e = f >> 4, q = f & 15;
        float4 v = ((const float4*)e_t)[(size_t)(j0 + e) * 16 + q];
        float* p = &As[e * ESTR + q * 4];
        p[0] = tf32r(v.x); p[1] = tf32r(v.y); p[2] = tf32r(v.z); p[3] = tf32r(v.w);
    }
    // dst_e cols 64..68
    for (int f = tid; f < 128 * 5; f += 256) {
        int e = f / 5, q = f - e * 5;
        As[e * ESTR + 64 + q] =
            (j0 + e < EH) ? tf32r(dst_e[(size_t)(j0 + e) * 5 + q]) : 0.0f;
    }
    if (tid < 128) {
        As[tid * ESTR + 101] = 0.0f;
        As[tid * ESTR + 102] = 0.0f;
        As[tid * ESTR + 103] = 0.0f;
        int j = j0 + tid;   // < 500096 <= EE, index reads always valid
        int s = edge_src[j];
        int d = edge_dst[j];
        float a0 = x_t[s * 3 + 0] - x_t[d * 3 + 0];
        float a1 = x_t[s * 3 + 1] - x_t[d * 3 + 1];
        float a2 = x_t[s * 3 + 2] - x_t[d * 3 + 2];
        dts[tid] = sqrtf(fmaxf(a0 * a0 + a1 * a1 + a2 * a2, 1e-8f));
        float c0 = dst_x[s * 3 + 0] - dst_x[d * 3 + 0];
        float c1 = dst_x[s * 3 + 1] - dst_x[d * 3 + 1];
        float c2 = dst_x[s * 3 + 2] - dst_x[d * 3 + 2];
        d1s[tid] = sqrtf(fmaxf(c0 * c0 + c1 * c1 + c2 * c2, 1e-8f));
    }
    __syncthreads();

    // rbf(d1) - rbf(dt), cols 69..100
    {
        int e = tid >> 1, k0 = (tid & 1) * 16;
        float v1 = d1s[e], vt = dts[e];
        #pragma unroll
        for (int kk = 0; kk < 16; kk++) {
            int k = k0 + kk;
            float mu = 10.0f * (float)k / 31.0f;
            float t1 = (v1 - mu) * INV_SIG;
            float t2 = (vt - mu) * INV_SIG;
            As[e * ESTR + 69 + k] = tf32r(__expf(-t1 * t1) - __expf(-t2 * t2));
        }
    }
    __syncthreads();

    const int w = tid >> 5, lane = tid & 31;
    const int g = lane >> 2, t = lane & 3;
    const int r0 = w * 16;

    float acc[8][4];
    #pragma unroll
    for (int nt = 0; nt < 8; nt++)
        #pragma unroll
        for (int q = 0; q < 4; q++)
            acc[nt][q] = 0.0f;

    #pragma unroll
    for (int ks = 0; ks < 13; ks++) {
        const int k0 = ks * 8;
        float a0 = As[(r0 + g) * ESTR + k0 + t];
        float a1 = As[(r0 + g + 8) * ESTR + k0 + t];
        float a2 = As[(r0 + g) * ESTR + k0 + t + 4];
        float a3 = As[(r0 + g + 8) * ESTR + k0 + t + 4];
        #pragma unroll
        for (int nt = 0; nt < 8; nt++) {
            int nnc = nt * 8 + g;
            float b0 = Ws[nnc * ESTR + k0 + t];
            float b1 = Ws[nnc * ESTR + k0 + t + 4];
            mma_tf32(acc[nt][0], acc[nt][1], acc[nt][2], acc[nt][3],
                     a0, a1, a2, a3, b0, b1);
        }
    }

    // epilogue: silu + bias, mirrored store
    #pragma unroll
    for (int nt = 0; nt < 8; nt++) {
        int col = nt * 8 + 2 * t;
        float b0v = bes[col], b1v = bes[col + 1];
        int j = j0 + r0 + g;
        if (j < EH) {
            float2 o;
            o.x = silu_f(acc[nt][0] + b0v);
            o.y = silu_f(acc[nt][1] + b1v);
            *(float2*)&edge_out[(size_t)j * 64 + col]        = o;
            *(float2*)&edge_out[(size_t)(j + EH) * 64 + col] = o;
        }
        int j2 = j + 8;
        if (j2 < EH) {
            float2 o;
            o.x = silu_f(acc[nt][2] + b0v);
            o.y = silu_f(acc[nt][3] + b1v);
            *(float2*)&edge_out[(size_t)j2 * 64 + col]        = o;
            *(float2*)&edge_out[(size_t)(j2 + EH) * 64 + col] = o;
        }
    }
}

// ---------------------------------------------------------------------------
// Host launch (inputs resolved by element count; same mapping as passing R1)
// ---------------------------------------------------------------------------
static int find_by_size(const int* sizes, int n, int target, int occurrence) {
    int seen = 0;
    for (int i = 0; i < n; i++)
        if (sizes[i] == target) {
            if (seen == occurrence) return i;
            seen++;
        }
    return -1;
}

extern "C" void kernel_launch(void* const* d_in, const int* in_sizes, int n_in,
                              void* d_out, int out_size)
{
    const float* s_t   = (const float*)d_in[find_by_size(in_sizes, n_in, NN * ND, 0)];
    const float* x_t   = (const float*)d_in[find_by_size(in_sizes, n_in, NN * 3, 0)];
    const float* dst_x = (const float*)d_in[find_by_size(in_sizes, n_in, NN * 3, 1)];
    const float* v_t   = (const float*)d_in[find_by_size(in_sizes, n_in, NN * 12, 0)];
    const float* dst_v = (const float*)d_in[find_by_size(in_sizes, n_in, NN * 12, 1)];
    const float* e_t   = (const float*)d_in[find_by_size(in_sizes, n_in, EE * 64, 0)];
    const float* dst_a = (const float*)d_in[find_by_size(in_sizes, n_in, NN * 16, 0)];
    const float* dst_e = (const float*)d_in[find_by_size(in_sizes, n_in, EH * 5, 0)];
    const int* edge_src = (const int*)d_in[find_by_size(in_sizes, n_in, EE, 0)];
    const int* edge_dst = (const int*)d_in[find_by_size(in_sizes, n_in, EE, 1)];
    const float* W_x = (const float*)d_in[find_by_size(in_sizes, n_in, 32 * 256, 0)];
    const float* W_v = (const float*)d_in[find_by_size(in_sizes, n_in, 16 * 256, 0)];
    const float* W_a = (const float*)d_in[find_by_size(in_sizes, n_in, 16 * 256, 1)];
    const float* W_n = (const float*)d_in[find_by_size(in_sizes, n_in, 256 * 256, 0)];
    const float* W_e = (const float*)d_in[find_by_size(in_sizes, n_in, 101 * 64, 0)];
    const float* b_x = (const float*)d_in[find_by_size(in_sizes, n_in, 256, 0)];
    const float* b_v = (const float*)d_in[find_by_size(in_sizes, n_in, 256, 1)];
    const float* b_a = (const float*)d_in[find_by_size(in_sizes, n_in, 256, 2)];
    const float* b_n = (const float*)d_in[find_by_size(in_sizes, n_in, 256, 3)];
    const float* b_e = (const float*)d_in[find_by_size(in_sizes, n_in, 64, 0)];

    float* out      = (float*)d_out;
    float* node_out = out;
    float* edge_out = out + (size_t)NN * ND;

    const int SMEM_NODE = (256 * USTR + 64 * USTR + 256 + 64) * 4;        // ~88 KB
    const int SMEM_EDGE = (64 * ESTR + 128 * ESTR + 64 + 128 + 128) * 4;  // ~84 KB

    cudaFuncSetAttribute(node_kernel,
                         cudaFuncAttributeMaxDynamicSharedMemorySize, SMEM_NODE);
    cudaFuncSetAttribute(edge_kernel,
                         cudaFuncAttributeMaxDynamicSharedMemorySize, SMEM_EDGE);

    precompute_kernel<<<65, 256>>>(W_x, W_v, W_a, b_x, b_v, b_a, W_n, b_n);
    edge_kernel<<<(EH + 127) / 128, 256, SMEM_EDGE>>>(
        e_t, dst_e, edge_src, edge_dst, x_t, dst_x, W_e, b_e, edge_out);
    node_kernel<<<(NN + 63) / 64, 256, SMEM_NODE>>>(
        s_t, x_t, v_t, dst_x, dst_v, dst_a, node_out);
}